// round 13
// baseline (speedup 1.0000x reference)
#include <cuda_runtime.h>

#define LSEQ 512
#define BSZ 1024
#define NTAG 64
#define START_TAG 62
#define END_TAG 63
#define GB 8   // batches per block (mma N dimension)

// ---- tf32 helpers ----
__device__ __forceinline__ unsigned to_tf32(float f) {
    unsigned r;
    asm("cvt.rna.tf32.f32 %0, %1;" : "=r"(r) : "f"(f));
    return r;
}
__device__ __forceinline__ void mma8(float& d0, float& d1, float& d2, float& d3,
                                     unsigned a0, unsigned a1, unsigned a2,
                                     unsigned a3, unsigned b0, unsigned b1) {
    asm("mma.sync.aligned.m16n8k8.row.col.f32.tf32.tf32.f32 "
        "{%0,%1,%2,%3}, {%4,%5,%6,%7}, {%8,%9}, {%0,%1,%2,%3};"
        : "+f"(d0), "+f"(d1), "+f"(d2), "+f"(d3)
        : "r"(a0), "r"(a1), "r"(a2), "r"(a3), "r"(b0), "r"(b1));
}

// ============================================================================
// Tensor-core CRF kernel. Block = 64 threads (2 warps) = 8 batches.
// Step: V'(64x8) = E(64x64) @ V(64x8) via m16n8k8 tf32 mma. E is CONSTANT:
// its A-fragments live in registers forever (2 m-tiles x 8 k-tiles x 4 regs
// = 64 regs/thread; warp w owns rows [32w,32w+32)). v moves through SMEM
// only as fragment relayout: 16 conflict-free LDS.32 + 4 STS.64 per warp-
// step for 8 batches (~5 MIO/batch-step vs ~36 in the best CUDA-core
// version -- the measured MIO wall of rounds 1-12).
// Precision: E in tf32 (bias ~1e-4 rel on output); V split V_hi + V_lo
// (both tf32, two accumulation chains) kills the per-step v-rounding error.
// Numerics otherwise = proven path: linear-domain, per-column renorm every
// 4 steps, deferred (maxw produced at l%4==3, consumed as 1/hi folded into
// exp(feat) + c += log(hi) at next l%4==0; preinit 1.0; no exit obligation).
// Fragment maps (PTX m16n8k8 tf32): A a0..a3 = (g,i)(g+8,i)(g,i+4)(g+8,i+4);
// B b0,b1 = (i,g)(i+4,g); D c0..c3 = (g,2i)(g,2i+1)(g+8,2i)(g+8,2i+1),
// g = lane>>2, i = lane&3.
// ============================================================================
__global__ void __launch_bounds__(64) crf_mma_kernel(
    const float* __restrict__ feats,
    const int*   __restrict__ tags,
    const float* __restrict__ mask,
    const float* __restrict__ transition,
    float* __restrict__ out)
{
    __shared__ __align__(16) float V[2][NTAG * GB];  // [pingpong][row*8+g]
    __shared__ float maxw[2][GB];
    __shared__ float endb[2][GB];
    __shared__ float apb[GB];

    const int tid  = threadIdx.x;
    const int w    = tid >> 5;
    const int lane = tid & 31;
    const int gID  = lane >> 2;
    const int tig  = lane & 3;
    const int bG   = blockIdx.x * GB;
    const int g0   = 2 * tig, g1 = g0 + 1;

    // ---- E fragments (constant): warp w covers rows [32w, 32w+32) ----
    unsigned A[2][8][4];
#pragma unroll
    for (int mt = 0; mt < 2; ++mt) {
        const int R0 = 32 * w + 16 * mt + gID, R1 = R0 + 8;
#pragma unroll
        for (int kt = 0; kt < 8; ++kt) {
            const int C0 = 8 * kt + tig, C1 = C0 + 4;
            A[mt][kt][0] = to_tf32(__expf(__ldg(transition + R0 * NTAG + C0)));
            A[mt][kt][1] = to_tf32(__expf(__ldg(transition + R1 * NTAG + C0)));
            A[mt][kt][2] = to_tf32(__expf(__ldg(transition + R0 * NTAG + C1)));
            A[mt][kt][3] = to_tf32(__expf(__ldg(transition + R1 * NTAG + C1)));
        }
    }

    // ---- V0 = one-hot(START) for all 8 columns ----
    for (int i = tid; i < NTAG * GB; i += 64)
        V[0][i] = ((i >> 3) == START_TAG) ? 1.0f : 0.0f;
    if (tid < 16) ((float*)maxw)[tid] = 1.0f;   // first renorm-consume no-op

    float cc0 = 0.0f, cc1 = 0.0f;    // log-offsets for columns g0, g1
    float myn[2][4];                 // this thread's latest v' elements

    // ---- prefetch rings (distance 2): feats (8 scalars) + mask pair ----
    float  fr[2][8];
    float2 mrr[2];
#pragma unroll
    for (int p = 0; p < 2; ++p) {
#pragma unroll
        for (int mt = 0; mt < 2; ++mt) {
            const int R0 = 32 * w + 16 * mt + gID, R1 = R0 + 8;
            fr[p][mt * 4 + 0] = __ldg(feats + ((size_t)p * BSZ + bG + g0) * NTAG + R0);
            fr[p][mt * 4 + 1] = __ldg(feats + ((size_t)p * BSZ + bG + g1) * NTAG + R0);
            fr[p][mt * 4 + 2] = __ldg(feats + ((size_t)p * BSZ + bG + g0) * NTAG + R1);
            fr[p][mt * 4 + 3] = __ldg(feats + ((size_t)p * BSZ + bG + g1) * NTAG + R1);
        }
        mrr[p] = *(const float2*)(mask + (size_t)p * BSZ + bG + g0);
    }
    __syncthreads();

#pragma unroll 4
    for (int l = 0; l < LSEQ; ++l) {
        const int u = l & 3;
        float fcur[8];
#pragma unroll
        for (int e = 0; e < 8; ++e) fcur[e] = fr[l & 1][e];
        const float2 mm = mrr[l & 1];

        {   // refill rings (distance 2)
            int ln = l + 2; if (ln > LSEQ - 1) ln = LSEQ - 1;
#pragma unroll
            for (int mt = 0; mt < 2; ++mt) {
                const int R0 = 32 * w + 16 * mt + gID, R1 = R0 + 8;
                fr[l & 1][mt * 4 + 0] = __ldg(feats + ((size_t)ln * BSZ + bG + g0) * NTAG + R0);
                fr[l & 1][mt * 4 + 1] = __ldg(feats + ((size_t)ln * BSZ + bG + g1) * NTAG + R0);
                fr[l & 1][mt * 4 + 2] = __ldg(feats + ((size_t)ln * BSZ + bG + g0) * NTAG + R1);
                fr[l & 1][mt * 4 + 3] = __ldg(feats + ((size_t)ln * BSZ + bG + g1) * NTAG + R1);
            }
            mrr[l & 1] = *(const float2*)(mask + (size_t)ln * BSZ + bG + g0);
        }

        // consume deferred renorm (every 4th step), per column
        float scale0 = 1.0f, scale1 = 1.0f;
        if (u == 0) {
            const float h0 = fmaxf(maxw[0][g0], maxw[1][g0]);
            const float h1 = fmaxf(maxw[0][g1], maxw[1][g1]);
            scale0 = __fdividef(1.0f, h0);  cc0 += __logf(h0);
            scale1 = __fdividef(1.0f, h1);  cc1 += __logf(h1);
        }

        // ---- load B operand (16 conflict-free LDS.32) ----
        const float* Vo = V[l & 1];
        float vF[16];
#pragma unroll
        for (int kt = 0; kt < 8; ++kt) {
            vF[2 * kt]     = Vo[(8 * kt + tig) * GB + gID];
            vF[2 * kt + 1] = Vo[(8 * kt + tig + 4) * GB + gID];
        }

        // ---- D = E @ (V_hi + V_lo): two f32-accumulated mma chains ----
        float dh[2][4] = {{0,0,0,0},{0,0,0,0}};
        float dl[2][4] = {{0,0,0,0},{0,0,0,0}};
#pragma unroll
        for (int kt = 0; kt < 8; ++kt) {
            const unsigned bh0 = to_tf32(vF[2 * kt]);
            const unsigned bh1 = to_tf32(vF[2 * kt + 1]);
            const unsigned bl0 = to_tf32(vF[2 * kt]     - __uint_as_float(bh0));
            const unsigned bl1 = to_tf32(vF[2 * kt + 1] - __uint_as_float(bh1));
            mma8(dh[0][0], dh[0][1], dh[0][2], dh[0][3],
                 A[0][kt][0], A[0][kt][1], A[0][kt][2], A[0][kt][3], bh0, bh1);
            mma8(dh[1][0], dh[1][1], dh[1][2], dh[1][3],
                 A[1][kt][0], A[1][kt][1], A[1][kt][2], A[1][kt][3], bh0, bh1);
            mma8(dl[0][0], dl[0][1], dl[0][2], dl[0][3],
                 A[0][kt][0], A[0][kt][1], A[0][kt][2], A[0][kt][3], bl0, bl1);
            mma8(dl[1][0], dl[1][1], dl[1][2], dl[1][3],
                 A[1][kt][0], A[1][kt][1], A[1][kt][2], A[1][kt][3], bl0, bl1);
        }

        // ---- epilogue: v' = D * exp(feat) * scale; mask-keep; store ----
        float* Vn = V[(l & 1) ^ 1];
        float lm0 = 0.0f, lm1 = 0.0f;
#pragma unroll
        for (int mt = 0; mt < 2; ++mt) {
            const int R0 = 32 * w + 16 * mt + gID, R1 = R0 + 8;
            float n00 = (dh[mt][0] + dl[mt][0]) * (__expf(fcur[mt*4+0]) * scale0);
            float n01 = (dh[mt][1] + dl[mt][1]) * (__expf(fcur[mt*4+1]) * scale1);
            float n10 = (dh[mt][2] + dl[mt][2]) * (__expf(fcur[mt*4+2]) * scale0);
            float n11 = (dh[mt][3] + dl[mt][3]) * (__expf(fcur[mt*4+3]) * scale1);
            if (mm.x == 0.0f || mm.y == 0.0f) {  // rare: masked step keeps old v
                const float2 vo0 = *(const float2*)&Vo[R0 * GB + g0];
                const float2 vo1 = *(const float2*)&Vo[R1 * GB + g0];
                if (mm.x == 0.0f) { n00 = vo0.x * scale0; n10 = vo1.x * scale0; }
                if (mm.y == 0.0f) { n01 = vo0.y * scale1; n11 = vo1.y * scale1; }
            }
            *(float2*)&Vn[R0 * GB + g0] = make_float2(n00, n01);
            *(float2*)&Vn[R1 * GB + g0] = make_float2(n10, n11);
            myn[mt][0] = n00; myn[mt][1] = n01; myn[mt][2] = n10; myn[mt][3] = n11;
            lm0 = fmaxf(lm0, fmaxf(n00, n10));
            lm1 = fmaxf(lm1, fmaxf(n01, n11));
        }

        if (u == 3) {   // produce next renorm factors (per-column warp max)
            lm0 = fmaxf(lm0, __shfl_xor_sync(0xffffffffu, lm0, 4));
            lm0 = fmaxf(lm0, __shfl_xor_sync(0xffffffffu, lm0, 8));
            lm0 = fmaxf(lm0, __shfl_xor_sync(0xffffffffu, lm0, 16));
            lm1 = fmaxf(lm1, __shfl_xor_sync(0xffffffffu, lm1, 4));
            lm1 = fmaxf(lm1, __shfl_xor_sync(0xffffffffu, lm1, 8));
            lm1 = fmaxf(lm1, __shfl_xor_sync(0xffffffffu, lm1, 16));
            if (lane < 4) { maxw[w][2 * lane] = lm0; maxw[w][2 * lane + 1] = lm1; }
        }
        __syncthreads();
    }

    // ---- allpath per column: c + log( sum_t v[t]*exp(T[END,t]) ) ----
    float s0 = 0.0f, s1 = 0.0f;
#pragma unroll
    for (int mt = 0; mt < 2; ++mt) {
        const int R0 = 32 * w + 16 * mt + gID, R1 = R0 + 8;
        const float e0 = __expf(__ldg(transition + END_TAG * NTAG + R0));
        const float e1 = __expf(__ldg(transition + END_TAG * NTAG + R1));
        s0 += myn[mt][0] * e0 + myn[mt][2] * e1;
        s1 += myn[mt][1] * e0 + myn[mt][3] * e1;
    }
    s0 += __shfl_xor_sync(0xffffffffu, s0, 4);
    s0 += __shfl_xor_sync(0xffffffffu, s0, 8);
    s0 += __shfl_xor_sync(0xffffffffu, s0, 16);
    s1 += __shfl_xor_sync(0xffffffffu, s1, 4);
    s1 += __shfl_xor_sync(0xffffffffu, s1, 8);
    s1 += __shfl_xor_sync(0xffffffffu, s1, 16);
    if (lane < 4) { endb[w][2 * lane] = s0; endb[w][2 * lane + 1] = s1; }

    // ---- realpath: 8 threads per batch, each sums 64 L-positions ----
    const int g   = tid >> 3;
    const int sub = tid & 7;
    const int b   = bG + g;
    float rsum = 0.0f, rlen = 0.0f;
    for (int i = 0; i < 64; ++i) {
        const int l = sub + 8 * i;
        int tag  = __ldg(tags + l * BSZ + b);
        int prev = (l == 0) ? START_TAG : __ldg(tags + (l - 1) * BSZ + b);
        float m  = __ldg(mask + l * BSZ + b);
        float emit = __ldg(feats + ((size_t)l * BSZ + b) * NTAG + tag);
        float tr   = __ldg(transition + tag * NTAG + prev);
        rsum += (emit + tr) * m;
        rlen += m;
    }
    rsum += __shfl_xor_sync(0xffffffffu, rsum, 1);
    rsum += __shfl_xor_sync(0xffffffffu, rsum, 2);
    rsum += __shfl_xor_sync(0xffffffffu, rsum, 4);
    rlen += __shfl_xor_sync(0xffffffffu, rlen, 1);
    rlen += __shfl_xor_sync(0xffffffffu, rlen, 2);
    rlen += __shfl_xor_sync(0xffffffffu, rlen, 4);
    __syncthreads();

    if (w == 0 && lane < 4) {
        apb[g0] = cc0 + __logf(endb[0][g0] + endb[1][g0]);
        apb[g1] = cc1 + __logf(endb[0][g1] + endb[1][g1]);
    }
    __syncthreads();

    if (sub == 0) {
        const int length = (int)(rlen + 0.5f);
        const int last = (length > 0) ? __ldg(tags + (length - 1) * BSZ + b)
                                      : START_TAG;
        const float real = rsum + __ldg(transition + END_TAG * NTAG + last);
        out[b] = apb[g] - real;
    }
}

extern "C" void kernel_launch(void* const* d_in, const int* in_sizes, int n_in,
                              void* d_out, int out_size) {
    const float* feats      = (const float*)d_in[0];
    const int*   tags       = (const int*)  d_in[1];
    const float* mask       = (const float*)d_in[2];
    const float* transition = (const float*)d_in[3];
    float* out = (float*)d_out;

    crf_mma_kernel<<<BSZ / GB, 64>>>(feats, tags, mask, transition, out);
}

// round 14
// speedup vs baseline: 1.0771x; 1.0771x over previous
#include <cuda_runtime.h>

#define LSEQ 512
#define BSZ 1024
#define NTAG 64
#define START_TAG 62
#define END_TAG 63
#define GB 8   // batches per group (mma N dimension)

// ---- tf32 helpers ----
__device__ __forceinline__ unsigned to_tf32(float f) {
    unsigned r;
    asm("cvt.rna.tf32.f32 %0, %1;" : "=r"(r) : "f"(f));
    return r;
}
__device__ __forceinline__ void mma8(float& d0, float& d1, float& d2, float& d3,
                                     unsigned a0, unsigned a1, unsigned a2,
                                     unsigned a3, unsigned b0, unsigned b1) {
    asm("mma.sync.aligned.m16n8k8.row.col.f32.tf32.tf32.f32 "
        "{%0,%1,%2,%3}, {%4,%5,%6,%7}, {%8,%9}, {%0,%1,%2,%3};"
        : "+f"(d0), "+f"(d1), "+f"(d2), "+f"(d3)
        : "r"(a0), "r"(a1), "r"(a2), "r"(a3), "r"(b0), "r"(b1));
}

// ============================================================================
// Tensor-core CRF kernel, M-SPLIT x4. Block = 128 threads (4 warps) = one
// group of 8 batches; grid = 128. Warp w owns output rows [16w, 16w+16):
// one m16n8k8 m-tile, A-fragments of E permanently in 32 regs.
//
// vs R13 (which validated numerics at rel_err 7e-7 but ran 1 warp/SMSP with
// a ~740-cycle serial chain): 4x the warps per group, mma work per warp /4,
// and the dependent accumulation chains split depth-8 -> 2 x depth-4
// (hi and lo each), shrinking the per-step critical path to ~300 cycles.
// Mask-keep now uses last step's register values (myn), not smem reads.
//
// Precision: E in tf32; V split V_hi + V_lo (two mma chains) -- proven.
// Numerics: linear-domain v' = (E @ v) * exp(feat) * scale; per-column
// renorm every 4 steps, deferred (maxw produced at l%4==3, consumed as
// 1/hi + c += log(hi) at next l%4==0; preinit 1.0; no exit obligation).
// Fragment maps (PTX m16n8k8 tf32): A a0..a3 = (g,i)(g+8,i)(g,i+4)(g+8,i+4);
// B b0,b1 = (i,g)(i+4,g); D c0..c3 = (g,2i)(g,2i+1)(g+8,2i)(g+8,2i+1),
// g = lane>>2, i = lane&3.
// ============================================================================
__global__ void __launch_bounds__(128) crf_mma_kernel(
    const float* __restrict__ feats,
    const int*   __restrict__ tags,
    const float* __restrict__ mask,
    const float* __restrict__ transition,
    float* __restrict__ out)
{
    __shared__ __align__(16) float V[2][NTAG * GB];  // [pingpong][row*8+col]
    __shared__ float maxw[4][GB];
    __shared__ float endb[4][GB];
    __shared__ float apb[GB];

    const int tid  = threadIdx.x;
    const int w    = tid >> 5;
    const int lane = tid & 31;
    const int gID  = lane >> 2;
    const int tig  = lane & 3;
    const int bG   = blockIdx.x * GB;
    const int g0   = 2 * tig, g1 = g0 + 1;     // D columns owned
    const int R0   = 16 * w + gID, R1 = R0 + 8; // D rows owned

    // ---- E fragments (constant): warp w covers rows [16w, 16w+16) ----
    unsigned A[8][4];
#pragma unroll
    for (int kt = 0; kt < 8; ++kt) {
        const int C0 = 8 * kt + tig, C1 = C0 + 4;
        A[kt][0] = to_tf32(__expf(__ldg(transition + R0 * NTAG + C0)));
        A[kt][1] = to_tf32(__expf(__ldg(transition + R1 * NTAG + C0)));
        A[kt][2] = to_tf32(__expf(__ldg(transition + R0 * NTAG + C1)));
        A[kt][3] = to_tf32(__expf(__ldg(transition + R1 * NTAG + C1)));
    }

    // ---- V0 = one-hot(START) for all 8 columns ----
    for (int i = tid; i < NTAG * GB; i += 128)
        V[0][i] = ((i >> 3) == START_TAG) ? 1.0f : 0.0f;
    if (tid < 32) ((float*)maxw)[tid] = 1.0f;   // first renorm-consume no-op

    float cc0 = 0.0f, cc1 = 0.0f;   // log-offsets for columns g0, g1
    float myn[4];                   // this thread's v' at (R0,g0)(R0,g1)(R1,g0)(R1,g1)
    myn[0] = myn[1] = (R0 == START_TAG) ? 1.0f : 0.0f;
    myn[2] = myn[3] = (R1 == START_TAG) ? 1.0f : 0.0f;

    // ---- prefetch rings (distance 2): 4 feat scalars + mask pair ----
    float  fr[2][4];
    float2 mrr[2];
#pragma unroll
    for (int p = 0; p < 2; ++p) {
        fr[p][0] = __ldg(feats + ((size_t)p * BSZ + bG + g0) * NTAG + R0);
        fr[p][1] = __ldg(feats + ((size_t)p * BSZ + bG + g1) * NTAG + R0);
        fr[p][2] = __ldg(feats + ((size_t)p * BSZ + bG + g0) * NTAG + R1);
        fr[p][3] = __ldg(feats + ((size_t)p * BSZ + bG + g1) * NTAG + R1);
        mrr[p] = *(const float2*)(mask + (size_t)p * BSZ + bG + g0);
    }
    __syncthreads();

#pragma unroll 4
    for (int l = 0; l < LSEQ; ++l) {
        const int u = l & 3;
        const float f0 = fr[l & 1][0], f1 = fr[l & 1][1];
        const float f2 = fr[l & 1][2], f3 = fr[l & 1][3];
        const float2 mm = mrr[l & 1];
        {   // refill rings (distance 2)
            int ln = l + 2; if (ln > LSEQ - 1) ln = LSEQ - 1;
            fr[l & 1][0] = __ldg(feats + ((size_t)ln * BSZ + bG + g0) * NTAG + R0);
            fr[l & 1][1] = __ldg(feats + ((size_t)ln * BSZ + bG + g1) * NTAG + R0);
            fr[l & 1][2] = __ldg(feats + ((size_t)ln * BSZ + bG + g0) * NTAG + R1);
            fr[l & 1][3] = __ldg(feats + ((size_t)ln * BSZ + bG + g1) * NTAG + R1);
            mrr[l & 1] = *(const float2*)(mask + (size_t)ln * BSZ + bG + g0);
        }

        // consume deferred renorm (every 4th step), per column
        float scale0 = 1.0f, scale1 = 1.0f;
        if (u == 0) {
            const float h0 = fmaxf(fmaxf(maxw[0][g0], maxw[1][g0]),
                                   fmaxf(maxw[2][g0], maxw[3][g0]));
            const float h1 = fmaxf(fmaxf(maxw[0][g1], maxw[1][g1]),
                                   fmaxf(maxw[2][g1], maxw[3][g1]));
            scale0 = __fdividef(1.0f, h0);  cc0 += __logf(h0);
            scale1 = __fdividef(1.0f, h1);  cc1 += __logf(h1);
        }

        // ---- load B operand (16 conflict-free LDS.32) ----
        const float* Vo = V[l & 1];
        float vF[16];
#pragma unroll
        for (int kt = 0; kt < 8; ++kt) {
            vF[2 * kt]     = Vo[(8 * kt + tig) * GB + gID];
            vF[2 * kt + 1] = Vo[(8 * kt + tig + 4) * GB + gID];
        }

        // ---- D = E @ (V_hi + V_lo): 4 parallel chains of depth 4 ----
        float dha[4] = {0,0,0,0}, dhb[4] = {0,0,0,0};
        float dla[4] = {0,0,0,0}, dlb[4] = {0,0,0,0};
#pragma unroll
        for (int kt = 0; kt < 4; ++kt) {
            const unsigned bh0 = to_tf32(vF[2 * kt]);
            const unsigned bh1 = to_tf32(vF[2 * kt + 1]);
            const unsigned bl0 = to_tf32(vF[2 * kt]     - __uint_as_float(bh0));
            const unsigned bl1 = to_tf32(vF[2 * kt + 1] - __uint_as_float(bh1));
            mma8(dha[0], dha[1], dha[2], dha[3],
                 A[kt][0], A[kt][1], A[kt][2], A[kt][3], bh0, bh1);
            mma8(dla[0], dla[1], dla[2], dla[3],
                 A[kt][0], A[kt][1], A[kt][2], A[kt][3], bl0, bl1);
        }
#pragma unroll
        for (int kt = 4; kt < 8; ++kt) {
            const unsigned bh0 = to_tf32(vF[2 * kt]);
            const unsigned bh1 = to_tf32(vF[2 * kt + 1]);
            const unsigned bl0 = to_tf32(vF[2 * kt]     - __uint_as_float(bh0));
            const unsigned bl1 = to_tf32(vF[2 * kt + 1] - __uint_as_float(bh1));
            mma8(dhb[0], dhb[1], dhb[2], dhb[3],
                 A[kt][0], A[kt][1], A[kt][2], A[kt][3], bh0, bh1);
            mma8(dlb[0], dlb[1], dlb[2], dlb[3],
                 A[kt][0], A[kt][1], A[kt][2], A[kt][3], bl0, bl1);
        }

        // ---- epilogue: v' = D * exp(feat) * scale; mask-keep from regs ----
        const float ef0 = __expf(f0) * scale0;
        const float ef1 = __expf(f1) * scale1;
        const float ef2 = __expf(f2) * scale0;
        const float ef3 = __expf(f3) * scale1;
        float n0 = ((dha[0] + dhb[0]) + (dla[0] + dlb[0])) * ef0;
        float n1 = ((dha[1] + dhb[1]) + (dla[1] + dlb[1])) * ef1;
        float n2 = ((dha[2] + dhb[2]) + (dla[2] + dlb[2])) * ef2;
        float n3 = ((dha[3] + dhb[3]) + (dla[3] + dlb[3])) * ef3;
        if (mm.x == 0.0f) { n0 = myn[0] * scale0; n2 = myn[2] * scale0; }
        if (mm.y == 0.0f) { n1 = myn[1] * scale1; n3 = myn[3] * scale1; }
        myn[0] = n0; myn[1] = n1; myn[2] = n2; myn[3] = n3;

        float* Vn = V[(l & 1) ^ 1];
        *(float2*)&Vn[R0 * GB + g0] = make_float2(n0, n1);
        *(float2*)&Vn[R1 * GB + g0] = make_float2(n2, n3);

        if (u == 3) {   // produce next renorm factors (per-column max)
            float lm0 = fmaxf(n0, n2), lm1 = fmaxf(n1, n3);
            lm0 = fmaxf(lm0, __shfl_xor_sync(0xffffffffu, lm0, 4));
            lm0 = fmaxf(lm0, __shfl_xor_sync(0xffffffffu, lm0, 8));
            lm0 = fmaxf(lm0, __shfl_xor_sync(0xffffffffu, lm0, 16));
            lm1 = fmaxf(lm1, __shfl_xor_sync(0xffffffffu, lm1, 4));
            lm1 = fmaxf(lm1, __shfl_xor_sync(0xffffffffu, lm1, 8));
            lm1 = fmaxf(lm1, __shfl_xor_sync(0xffffffffu, lm1, 16));
            if (lane < 4) { maxw[w][2 * lane] = lm0; maxw[w][2 * lane + 1] = lm1; }
        }
        __syncthreads();
    }

    // ---- allpath per column: c + log( sum_t v[t]*exp(T[END,t]) ) ----
    {
        const float e0 = __expf(__ldg(transition + END_TAG * NTAG + R0));
        const float e1 = __expf(__ldg(transition + END_TAG * NTAG + R1));
        float s0 = myn[0] * e0 + myn[2] * e1;
        float s1 = myn[1] * e0 + myn[3] * e1;
        s0 += __shfl_xor_sync(0xffffffffu, s0, 4);
        s0 += __shfl_xor_sync(0xffffffffu, s0, 8);
        s0 += __shfl_xor_sync(0xffffffffu, s0, 16);
        s1 += __shfl_xor_sync(0xffffffffu, s1, 4);
        s1 += __shfl_xor_sync(0xffffffffu, s1, 8);
        s1 += __shfl_xor_sync(0xffffffffu, s1, 16);
        if (lane < 4) { endb[w][2 * lane] = s0; endb[w][2 * lane + 1] = s1; }
    }
    __syncthreads();
    if (tid < 4) {   // w==0, tig==tid: owns columns 2*tid, 2*tid+1 (cc0/cc1)
        const int ca = 2 * tid, cb = ca + 1;
        apb[ca] = cc0 + __logf((endb[0][ca] + endb[1][ca]) +
                               (endb[2][ca] + endb[3][ca]));
        apb[cb] = cc1 + __logf((endb[0][cb] + endb[1][cb]) +
                               (endb[2][cb] + endb[3][cb]));
    }

    // ---- realpath: 16 threads per batch, each sums 32 L-positions ----
    const int g   = tid >> 4;
    const int sub = tid & 15;
    const int b   = bG + g;
    float rsum = 0.0f, rlen = 0.0f;
#pragma unroll 4
    for (int i = 0; i < 32; ++i) {
        const int l = sub + 16 * i;
        int tag  = __ldg(tags + l * BSZ + b);
        int prev = (l == 0) ? START_TAG : __ldg(tags + (l - 1) * BSZ + b);
        float m  = __ldg(mask + l * BSZ + b);
        float emit = __ldg(feats + ((size_t)l * BSZ + b) * NTAG + tag);
        float tr   = __ldg(transition + tag * NTAG + prev);
        rsum += (emit + tr) * m;
        rlen += m;
    }
#pragma unroll
    for (int o = 8; o > 0; o >>= 1) {
        rsum += __shfl_xor_sync(0xffffffffu, rsum, o);
        rlen += __shfl_xor_sync(0xffffffffu, rlen, o);
    }
    __syncthreads();

    if (sub == 0) {
        const int length = (int)(rlen + 0.5f);
        const int last = (length > 0) ? __ldg(tags + (length - 1) * BSZ + b)
                                      : START_TAG;
        const float real = rsum + __ldg(transition + END_TAG * NTAG + last);
        out[b] = apb[g] - real;
    }
}

extern "C" void kernel_launch(void* const* d_in, const int* in_sizes, int n_in,
                              void* d_out, int out_size) {
    const float* feats      = (const float*)d_in[0];
    const int*   tags       = (const int*)  d_in[1];
    const float* mask       = (const float*)d_in[2];
    const float* transition = (const float*)d_in[3];
    float* out = (float*)d_out;

    crf_mma_kernel<<<BSZ / GB, 128>>>(feats, tags, mask, transition, out);
}